// round 6
// baseline (speedup 1.0000x reference)
#include <cuda_runtime.h>
#include <cstdint>

// USR_EMB: out[row] = emb[searchsorted(userlist, x[row])], 64 f32/row.
// R5 post-mortem: two different structures plateau at ~39us with L1tex the
// hottest unit (70%) -> suspect SM-side store path (per-lane STG.128
// wavefronts + 12cyc issue). R6: stage each CTA's 128 contiguous output rows
// (32KB) in smem via LDG.128->STS.128, then ONE cp.async.bulk (UBLKCP)
// smem->gmem per tile. Removes all global-store wavefronts from L1tex.
// Gathers use .cg (no L1 alloc; ~0% hit rate). Index phase unchanged
// (verified u+1 fast path, binary-search fallback).

static constexpr int EMB   = 64;
static constexpr int CPR   = EMB / 4;   // 16 float4 chunks per row
static constexpr int TROWS = 128;       // rows per CTA tile
static constexpr int RPW   = 16;        // rows per warp (8 warps)
static constexpr int TILE_BYTES = TROWS * EMB * 4;  // 32KB

__global__ void __launch_bounds__(256) usr_emb_kernel(
    const int* __restrict__ x,
    const int* __restrict__ userlist,
    const float4* __restrict__ emb,      // [emb_rows][16] float4
    float4* __restrict__ out,            // [n_rows][16] float4
    int n_rows, int n_userlist, int emb_rows)
{
    __shared__ float4 tile[TROWS * CPR];             // 32KB staging, out layout

    int warpInCta = threadIdx.x >> 5;
    int lane      = threadIdx.x & 31;
    int group     = lane >> 4;           // which 8-row half this thread moves
    int chunk     = lane & 15;           // float4 within row

    int tileRow0 = blockIdx.x * TROWS;
    int wrow0    = tileRow0 + warpInCta * RPW;
    bool fullTile = (tileRow0 + TROWS) <= n_rows;

    // ---- Cooperative index computation: lanes 0-15, one row each ----
    int myIdx = 0;
    if (lane < RPW) {
        int r = wrow0 + lane;
        int u = (r < n_rows) ? __ldcs(&x[r]) : 0;    // coalesced, read-once
        // Fast path: userlist = [-1, 0..N-1] => searchsorted(u) = u+1.
        // Verified against data; binary-search fallback for generality.
        int i = u + 1;
        bool ok = (i >= 1) && (i < n_userlist)
                  && (__ldg(&userlist[i]) == u)
                  && (__ldg(&userlist[i - 1]) < u);
        if (!ok) {
            int lo = 0, hi = n_userlist;
            while (lo < hi) {
                int mid = (lo + hi) >> 1;
                if (__ldg(&userlist[mid]) < u) lo = mid + 1; else hi = mid;
            }
            i = lo;
        }
        if (i >= emb_rows) i = emb_rows - 1;
        if (i < 0) i = 0;
        myIdx = i;
    }
    __syncwarp();

    int idx[8];
#pragma unroll
    for (int k = 0; k < 8; k++)
        idx[k] = __shfl_sync(0xffffffffu, myIdx, group * 8 + k);

    int slotBase = warpInCta * RPW + group * 8;      // row slot within tile

    if (fullTile) {
        // ---- Gather -> smem staging (two batches of 4 independent LDGs) ----
#pragma unroll
        for (int b = 0; b < 2; b++) {
            float4 v[4];
#pragma unroll
            for (int k = 0; k < 4; k++)
                v[k] = __ldcg(&emb[(size_t)idx[b * 4 + k] * CPR + chunk]);
#pragma unroll
            for (int k = 0; k < 4; k++)
                tile[(slotBase + b * 4 + k) * CPR + chunk] = v[k];
        }
        __syncthreads();

        // ---- One bulk smem->gmem copy for the whole 32KB tile ----
        if (threadIdx.x == 0) {
            asm volatile("fence.proxy.async.shared::cta;" ::: "memory");
            uint32_t saddr;
            asm("{ .reg .u64 t; cvta.to.shared.u64 t, %1; cvt.u32.u64 %0, t; }"
                : "=r"(saddr) : "l"(tile));
            void* dst = (void*)(out + (size_t)tileRow0 * CPR);
            asm volatile(
                "cp.async.bulk.global.shared::cta.bulk_group [%0], [%1], %2;"
                :: "l"(dst), "r"(saddr), "r"((uint32_t)TILE_BYTES)
                : "memory");
            asm volatile("cp.async.bulk.commit_group;" ::: "memory");
            asm volatile("cp.async.bulk.wait_group.read 0;" ::: "memory");
        }
    } else {
        // Guarded tail path (generic shapes): direct streaming stores.
#pragma unroll
        for (int b = 0; b < 2; b++) {
            float4 v[4];
#pragma unroll
            for (int k = 0; k < 4; k++) {
                int r = wrow0 + group * 8 + b * 4 + k;
                v[k] = (r < n_rows) ? __ldcg(&emb[(size_t)idx[b * 4 + k] * CPR + chunk])
                                    : make_float4(0.f, 0.f, 0.f, 0.f);
            }
#pragma unroll
            for (int k = 0; k < 4; k++) {
                int r = wrow0 + group * 8 + b * 4 + k;
                if (r < n_rows)
                    __stcs(&out[(size_t)r * CPR + chunk], v[k]);
            }
        }
    }
}

extern "C" void kernel_launch(void* const* d_in, const int* in_sizes, int n_in,
                              void* d_out, int out_size)
{
    const int*   x        = (const int*)d_in[0];    // [B*H] int32
    const int*   userlist = (const int*)d_in[1];    // [N+1] int32
    const float* emb      = (const float*)d_in[2];  // [(N+1)*64] f32

    int n_rows     = in_sizes[0];          // 819200
    int n_userlist = in_sizes[1];          // 100001
    int emb_rows   = in_sizes[2] / EMB;    // 100001

    int grid = (n_rows + TROWS - 1) / TROWS;         // 6400
    usr_emb_kernel<<<grid, 256>>>(x, userlist, (const float4*)emb,
                                  (float4*)d_out, n_rows, n_userlist, emb_rows);
}

// round 7
// speedup vs baseline: 1.4239x; 1.4239x over previous
#include <cuda_runtime.h>
#include <cstdint>

// USR_EMB: out[row] = emb[searchsorted(userlist, x[row])], 64 f32/row.
// R6 post-mortem: bulk-copy staging regressed (extra smem pass + sync);
// plateau is the LTS data path (~420MB through L2 at ~95% of measured cap).
// R7 = revert to the best structure (R4: warp-cooperative indexing, 8
// rows/thread) with two shavings: .cg gathers (no L1 allocation — random
// reads over 25.6MB never hit 228KB L1) and all 8 gathers issued in one
// burst (MLP=8) before the 8 streaming stores.

static constexpr int EMB = 64;
static constexpr int CPR = EMB / 4;  // 16 float4 chunks per row
static constexpr int RPW = 16;       // rows per warp

__global__ void __launch_bounds__(256) usr_emb_kernel(
    const int* __restrict__ x,
    const int* __restrict__ userlist,
    const float4* __restrict__ emb,      // [emb_rows][16] float4
    float4* __restrict__ out,            // [n_rows][16] float4
    int n_rows, int n_userlist, int emb_rows)
{
    int warpId = (blockIdx.x * blockDim.x + threadIdx.x) >> 5;
    int lane   = threadIdx.x & 31;
    int group  = lane >> 4;              // which 8-row half this thread moves
    int chunk  = lane & 15;              // float4 within row
    int wrow0  = warpId * RPW;
    if (wrow0 >= n_rows) return;

    // ---- Cooperative index computation: lanes 0-15, one row each ----
    int myIdx = 0;
    if (lane < RPW) {
        int r = wrow0 + lane;
        int u = (r < n_rows) ? __ldcs(&x[r]) : 0;   // coalesced 64B, read-once
        // Fast path: userlist = [-1, 0..N-1] => searchsorted(u) = u+1.
        // Verified against data; binary-search fallback for generality.
        int i = u + 1;
        bool ok = (i >= 1) && (i < n_userlist)
                  && (__ldg(&userlist[i]) == u)
                  && (__ldg(&userlist[i - 1]) < u);
        if (!ok) {
            int lo = 0, hi = n_userlist;
            while (lo < hi) {
                int mid = (lo + hi) >> 1;
                if (__ldg(&userlist[mid]) < u) lo = mid + 1; else hi = mid;
            }
            i = lo;
        }
        if (i >= emb_rows) i = emb_rows - 1;
        if (i < 0) i = 0;
        myIdx = i;
    }
    __syncwarp();

    // Each thread pulls its 8 row-indices from the computing lanes.
    int idx[8];
#pragma unroll
    for (int k = 0; k < 8; k++)
        idx[k] = __shfl_sync(0xffffffffu, myIdx, group * 8 + k);

    int rowBase = wrow0 + group * 8;

    // ---- 8 independent gathers in one burst (MLP=8), L2-hit, no L1 alloc --
    float4 v[8];
#pragma unroll
    for (int k = 0; k < 8; k++)
        v[k] = __ldcg(&emb[(size_t)idx[k] * CPR + chunk]);

    // ---- 8 coalesced streaming stores (evict-first; never re-read) ----
#pragma unroll
    for (int k = 0; k < 8; k++) {
        int r = rowBase + k;
        if (r < n_rows)
            __stcs(&out[(size_t)r * CPR + chunk], v[k]);
    }
}

extern "C" void kernel_launch(void* const* d_in, const int* in_sizes, int n_in,
                              void* d_out, int out_size)
{
    const int*   x        = (const int*)d_in[0];    // [B*H] int32
    const int*   userlist = (const int*)d_in[1];    // [N+1] int32
    const float* emb      = (const float*)d_in[2];  // [(N+1)*64] f32

    int n_rows     = in_sizes[0];          // 819200
    int n_userlist = in_sizes[1];          // 100001
    int emb_rows   = in_sizes[2] / EMB;    // 100001

    int n_warps = (n_rows + RPW - 1) / RPW;          // 51200
    long long total_threads = (long long)n_warps * 32;
    int block = 256;
    int grid  = (int)((total_threads + block - 1) / block);  // 6400

    usr_emb_kernel<<<grid, block>>>(x, userlist, (const float4*)emb,
                                    (float4*)d_out, n_rows, n_userlist, emb_rows);
}